// round 13
// baseline (speedup 1.0000x reference)
#include <cuda_runtime.h>
#include <cuda_fp16.h>
#include <math.h>
#include <stdint.h>

// ---------------- problem constants ----------------
#define NE   16      // experts
#define NT   2048    // tokens per expert
#define DD   1024    // model dim
#define HH   4096    // hidden dim

// ---------------- scratch (device globals; allocation-guard legal) ----------
__device__ __half g_x  [(size_t)NE * NT * DD];   // [e][t][d]
__device__ __half g_w1t[(size_t)NE * HH * DD];   // [e][h][d]
__device__ __half g_w2t[(size_t)NE * DD * HH];   // [e][d][h]
__device__ __half g_h  [(size_t)NE * NT * HH];   // [e][t][h]

// ---------------- helpers ----------------
__device__ __forceinline__ uint32_t smem_u32(const void* p) {
    uint32_t a;
    asm("{ .reg .u64 t; cvta.to.shared.u64 t, %1; cvt.u32.u64 %0, t; }" : "=r"(a) : "l"(p));
    return a;
}

__device__ __forceinline__ void cp16(uint32_t dst, const void* src) {
    asm volatile("cp.async.cg.shared.global [%0], [%1], 16;" :: "r"(dst), "l"(src));
}
#define CP_COMMIT() asm volatile("cp.async.commit_group;" ::: "memory")

__device__ __forceinline__ void ldsm4(uint32_t* r, uint32_t addr) {
    asm volatile("ldmatrix.sync.aligned.m8n8.x4.shared.b16 {%0,%1,%2,%3}, [%4];"
                 : "=r"(r[0]), "=r"(r[1]), "=r"(r[2]), "=r"(r[3]) : "r"(addr));
}

__device__ __forceinline__ void mma16816(float* d, const uint32_t* a,
                                         const uint32_t b0, const uint32_t b1) {
    asm volatile(
        "mma.sync.aligned.m16n8k16.row.col.f32.f16.f16.f32 "
        "{%0,%1,%2,%3}, {%4,%5,%6,%7}, {%8,%9}, {%0,%1,%2,%3};"
        : "+f"(d[0]), "+f"(d[1]), "+f"(d[2]), "+f"(d[3])
        : "r"(a[0]), "r"(a[1]), "r"(a[2]), "r"(a[3]), "r"(b0), "r"(b1));
}

// swizzle for 128B-row tiles: 16B chunk XORed with (row & 7)
__device__ __forceinline__ uint32_t swz(uint32_t row, uint32_t ch) {
    return row * 128u + ((ch ^ (row & 7u)) << 4);
}

// ---------------- conversion kernels ----------------
__global__ void convert_h_kernel(const float* __restrict__ in,
                                 __half* __restrict__ out, size_t n4) {
    size_t i = (size_t)blockIdx.x * blockDim.x + threadIdx.x;
    if (i >= n4) return;
    float4 v = reinterpret_cast<const float4*>(in)[i];
    reinterpret_cast<ushort4*>(out)[i] = make_ushort4(
        __half_as_ushort(__float2half_rn(v.x)), __half_as_ushort(__float2half_rn(v.y)),
        __half_as_ushort(__float2half_rn(v.z)), __half_as_ushort(__float2half_rn(v.w)));
}

// in: [E][R][C] fp32, out: [E][C][R] fp16
__global__ void transpose_h_kernel(const float* __restrict__ in,
                                   __half* __restrict__ out, int R, int C) {
    __shared__ float tile[32][33];
    int e = blockIdx.z;
    int c0 = blockIdx.x * 32, r0 = blockIdx.y * 32;
    int tx = threadIdx.x, ty = threadIdx.y;   // 32 x 8
    const float* pin = in + (size_t)e * R * C;
    #pragma unroll
    for (int j = 0; j < 4; j++)
        tile[ty + 8 * j][tx] = pin[(size_t)(r0 + ty + 8 * j) * C + c0 + tx];
    __syncthreads();
    __half* pout = out + (size_t)e * R * C;
    #pragma unroll
    for (int j = 0; j < 4; j++) {
        size_t o = (size_t)(c0 + ty + 8 * j) * R + r0 + tx;
        pout[o] = __float2half_rn(tile[tx][ty + 8 * j]);
    }
}

// ---------------- fp16 mma.sync GEMM ----------------
// CTA tile 128 (M=tokens) x 128 (N=features), 256 threads, warp tile 64x32.
// BK=64 (128B rows), 3-stage cp.async pipeline, 2 CTAs resident per SM.
// Register-pipelined fragments: A double-buffered across k16 steps,
// B consumed directly from ldmatrix output (no repack).
// C[t][f] = sum_k A[t][k] * B[f][k]
template <int KTOT, int F, bool GELU>
__global__ __launch_bounds__(256, 2)
void gemm_h_kernel(const __half* __restrict__ A,
                   const __half* __restrict__ B,
                   const float* __restrict__ bias,
                   float* __restrict__ outF,
                   __half* __restrict__ outH) {
    constexpr int S  = 3;
    constexpr int BK = 64;                    // 128B rows
    constexpr int NK = KTOT / BK;
    constexpr uint32_t OFF_A = 0;             // A: 128 rows x 128B = 16 KB
    constexpr uint32_t OFF_B = 16384;         // B: 128 rows x 128B = 16 KB
    constexpr uint32_t STAGE_B = 32768;       // 32 KB

    extern __shared__ char dynsmem[];
    const uint32_t sm0 = smem_u32(dynsmem);

    const int tid  = threadIdx.x;
    const int wid  = tid >> 5;
    const int lane = tid & 31;
    const int wm   = wid & 1;      // 2 warp rows  (M: 64 each)
    const int wn   = wid >> 1;     // 4 warp cols  (N: 32 each)

    const int m0 = blockIdx.y * 128;
    const int n0 = blockIdx.x * 128;
    const __half* pA = A + (size_t)blockIdx.z * NT * KTOT + (size_t)m0 * KTOT;
    const __half* pB = B + (size_t)blockIdx.z * F  * KTOT + (size_t)n0 * KTOT;

    // ---- precomputed cp.async offsets (256 threads) ----
    // each tile: 128 rows x 8 chunks = 1024 slots -> 4 per thread per tile
    uint32_t dstT[4]; uint32_t srcT[4];       // byte offsets
    #pragma unroll
    for (int l = 0; l < 4; l++) {
        int idx = l * 256 + tid, row = idx >> 3, ch = idx & 7;
        dstT[l] = swz(row, ch);
        srcT[l] = (uint32_t)(row * KTOT + ch * 8) * 2u;   // bytes
    }

    auto load_chunk = [&](uint32_t sb, int k0) {
        const char* bA = reinterpret_cast<const char*>(pA + k0);
        const char* bB = reinterpret_cast<const char*>(pB + k0);
        #pragma unroll
        for (int l = 0; l < 4; l++)
            cp16(sb + OFF_A + dstT[l], bA + srcT[l]);
        #pragma unroll
        for (int l = 0; l < 4; l++)
            cp16(sb + OFF_B + dstT[l], bB + srcT[l]);
        CP_COMMIT();
    };

    // ---- precomputed ldmatrix offsets (k16 step via ^ (k16<<5)) ----
    const int lrow = lane & 15;
    const int lch  = lane >> 4;
    uint32_t offA[4], offB[2];
    #pragma unroll
    for (int mt = 0; mt < 4; mt++)
        offA[mt] = OFF_A + swz((uint32_t)(wm * 64 + mt * 16 + lrow), (uint32_t)lch);
    #pragma unroll
    for (int nb = 0; nb < 2; nb++)
        offB[nb] = OFF_B + swz((uint32_t)(wn * 32 + nb * 16 + lrow), (uint32_t)lch);

    float acc[4][4][4];
    #pragma unroll
    for (int i = 0; i < 4; i++)
        #pragma unroll
        for (int j = 0; j < 4; j++)
            #pragma unroll
            for (int c = 0; c < 4; c++) acc[i][j][c] = 0.f;

    // prefill
    load_chunk(sm0, 0);
    load_chunk(sm0 + STAGE_B, BK);

    uint32_t csb = sm0;                    // compute stage base
    uint32_t lsb = sm0 + 2 * STAGE_B;      // load stage base

    uint32_t a[2][4][4];                   // double-buffered A frags

    #pragma unroll 1
    for (int i = 0; i < NK; i++) {
        asm volatile("cp.async.wait_group %0;" :: "n"(S - 2) : "memory");
        __syncthreads();

        const int j = i + S - 1;
        if (j < NK) {
            load_chunk(lsb, j * BK);
            lsb += STAGE_B; if (lsb == sm0 + 3 * STAGE_B) lsb = sm0;
        } else {
            CP_COMMIT();
        }

        // prefetch A frags for k16 = 0
        #pragma unroll
        for (int mt = 0; mt < 4; mt++) ldsm4(a[0][mt], csb + offA[mt]);

        #pragma unroll
        for (int k16 = 0; k16 < 4; k16++) {
            const int cur = k16 & 1;
            const uint32_t kx  = (uint32_t)k16 << 5;
            const uint32_t kxn = (uint32_t)(k16 + 1) << 5;
            uint32_t u0[4], u1[4];
            ldsm4(u0, csb + (offB[0] ^ kx));    // n-tiles 0,1
            ldsm4(u1, csb + (offB[1] ^ kx));    // n-tiles 2,3
            #pragma unroll
            for (int mt = 0; mt < 4; mt++) {
                mma16816(acc[mt][0], a[cur][mt], u0[0], u0[2]);
                mma16816(acc[mt][1], a[cur][mt], u0[1], u0[3]);
                mma16816(acc[mt][2], a[cur][mt], u1[0], u1[2]);
                mma16816(acc[mt][3], a[cur][mt], u1[1], u1[3]);
                if (k16 < 3)                      // interleaved A prefetch
                    ldsm4(a[cur ^ 1][mt], csb + (offA[mt] ^ kxn));
            }
        }
        csb += STAGE_B; if (csb == sm0 + 3 * STAGE_B) csb = sm0;
    }

    // ---------------- epilogue ----------------
    const size_t eOut = (size_t)blockIdx.z * NT * F;
    #pragma unroll
    for (int mt = 0; mt < 4; mt++) {
        #pragma unroll
        for (int nt = 0; nt < 4; nt++) {
            const int n = n0 + wn * 32 + nt * 8 + (lane & 3) * 2;
            const float2 bv = *reinterpret_cast<const float2*>(&bias[n]);
            #pragma unroll
            for (int half = 0; half < 2; half++) {
                const int m = m0 + wm * 64 + mt * 16 + (lane >> 2) + half * 8;
                float v0 = acc[mt][nt][2 * half + 0] + bv.x;
                float v1 = acc[mt][nt][2 * half + 1] + bv.y;
                const size_t o = eOut + (size_t)m * F + n;
                if (GELU) {
                    v0 = 0.5f * v0 * (1.0f + erff(v0 * 0.70710678118654752f));
                    v1 = 0.5f * v1 * (1.0f + erff(v1 * 0.70710678118654752f));
                    *reinterpret_cast<ushort2*>(&outH[o]) = make_ushort2(
                        __half_as_ushort(__float2half_rn(v0)),
                        __half_as_ushort(__float2half_rn(v1)));
                } else {
                    *reinterpret_cast<float2*>(&outF[o]) = make_float2(v0, v1);
                }
            }
        }
    }
}

// ---------------- launch ----------------
extern "C" void kernel_launch(void* const* d_in, const int* in_sizes, int n_in,
                              void* d_out, int out_size) {
    const float* x  = (const float*)d_in[0];
    const float* w1 = (const float*)d_in[1];
    const float* w2 = (const float*)d_in[2];
    const float* b1 = (const float*)d_in[3];
    const float* b2 = (const float*)d_in[4];
    float* out = (float*)d_out;

    __half *xh, *w1t, *w2t, *hid;
    cudaGetSymbolAddress((void**)&xh,  g_x);
    cudaGetSymbolAddress((void**)&w1t, g_w1t);
    cudaGetSymbolAddress((void**)&w2t, g_w2t);
    cudaGetSymbolAddress((void**)&hid, g_h);

    // 1) cast x -> fp16
    {
        size_t n4 = (size_t)NE * NT * DD / 4;
        convert_h_kernel<<<(unsigned)((n4 + 255) / 256), 256>>>(x, xh, n4);
    }
    // 2) transpose+cast w1: [e][DD][HH] -> [e][HH][DD]
    transpose_h_kernel<<<dim3(HH / 32, DD / 32, NE), dim3(32, 8)>>>(w1, w1t, DD, HH);
    // 3) transpose+cast w2: [e][HH][DD] -> [e][DD][HH]
    transpose_h_kernel<<<dim3(DD / 32, HH / 32, NE), dim3(32, 8)>>>(w2, w2t, HH, DD);

    const int SMEM_BYTES = 3 * 32768;   // 96 KB per CTA
    cudaFuncSetAttribute(gemm_h_kernel<DD, HH, true>,
                         cudaFuncAttributeMaxDynamicSharedMemorySize, SMEM_BYTES);
    cudaFuncSetAttribute(gemm_h_kernel<HH, DD, false>,
                         cudaFuncAttributeMaxDynamicSharedMemorySize, SMEM_BYTES);

    // 4) GEMM1: hidden[t][h] = gelu(x @ w1 + b1)
    gemm_h_kernel<DD, HH, true><<<dim3(HH / 128, NT / 128, NE), 256, SMEM_BYTES>>>(
        xh, w1t, b1, nullptr, hid);

    // 5) GEMM2: out[t][d] = hidden @ w2 + b2
    gemm_h_kernel<HH, DD, false><<<dim3(DD / 128, NT / 128, NE), 256, SMEM_BYTES>>>(
        hid, w2t, b2, out, nullptr);
}

// round 15
// speedup vs baseline: 1.0016x; 1.0016x over previous
#include <cuda_runtime.h>
#include <cuda_fp16.h>
#include <math.h>
#include <stdint.h>

// ---------------- problem constants ----------------
#define NE   16      // experts
#define NT   2048    // tokens per expert
#define DD   1024    // model dim
#define HH   4096    // hidden dim

// ---------------- scratch (device globals; allocation-guard legal) ----------
__device__ __half g_x  [(size_t)NE * NT * DD];   // [e][t][d]
__device__ __half g_w1t[(size_t)NE * HH * DD];   // [e][h][d]
__device__ __half g_w2t[(size_t)NE * DD * HH];   // [e][d][h]
__device__ __half g_h  [(size_t)NE * NT * HH];   // [e][t][h]

// ---------------- helpers ----------------
__device__ __forceinline__ uint32_t smem_u32(const void* p) {
    uint32_t a;
    asm("{ .reg .u64 t; cvta.to.shared.u64 t, %1; cvt.u32.u64 %0, t; }" : "=r"(a) : "l"(p));
    return a;
}

__device__ __forceinline__ void cp16(uint32_t dst, const void* src) {
    asm volatile("cp.async.cg.shared.global [%0], [%1], 16;" :: "r"(dst), "l"(src));
}
#define CP_COMMIT() asm volatile("cp.async.commit_group;" ::: "memory")

__device__ __forceinline__ void ldsm4(uint32_t* r, uint32_t addr) {
    asm volatile("ldmatrix.sync.aligned.m8n8.x4.shared.b16 {%0,%1,%2,%3}, [%4];"
                 : "=r"(r[0]), "=r"(r[1]), "=r"(r[2]), "=r"(r[3]) : "r"(addr));
}

__device__ __forceinline__ void mma16816(float* d, const uint32_t* a,
                                         const uint32_t b0, const uint32_t b1) {
    asm volatile(
        "mma.sync.aligned.m16n8k16.row.col.f32.f16.f16.f32 "
        "{%0,%1,%2,%3}, {%4,%5,%6,%7}, {%8,%9}, {%0,%1,%2,%3};"
        : "+f"(d[0]), "+f"(d[1]), "+f"(d[2]), "+f"(d[3])
        : "r"(a[0]), "r"(a[1]), "r"(a[2]), "r"(a[3]), "r"(b0), "r"(b1));
}

// swizzle for 128B-row tiles: 16B chunk XORed with (row & 7)
__device__ __forceinline__ uint32_t swz(uint32_t row, uint32_t ch) {
    return row * 128u + ((ch ^ (row & 7u)) << 4);
}

// ---------------- conversion kernels ----------------
__global__ void convert_h_kernel(const float* __restrict__ in,
                                 __half* __restrict__ out, size_t n4) {
    size_t i = (size_t)blockIdx.x * blockDim.x + threadIdx.x;
    if (i >= n4) return;
    float4 v = reinterpret_cast<const float4*>(in)[i];
    reinterpret_cast<ushort4*>(out)[i] = make_ushort4(
        __half_as_ushort(__float2half_rn(v.x)), __half_as_ushort(__float2half_rn(v.y)),
        __half_as_ushort(__float2half_rn(v.z)), __half_as_ushort(__float2half_rn(v.w)));
}

// in: [E][R][C] fp32, out: [E][C][R] fp16
__global__ void transpose_h_kernel(const float* __restrict__ in,
                                   __half* __restrict__ out, int R, int C) {
    __shared__ float tile[32][33];
    int e = blockIdx.z;
    int c0 = blockIdx.x * 32, r0 = blockIdx.y * 32;
    int tx = threadIdx.x, ty = threadIdx.y;   // 32 x 8
    const float* pin = in + (size_t)e * R * C;
    #pragma unroll
    for (int j = 0; j < 4; j++)
        tile[ty + 8 * j][tx] = pin[(size_t)(r0 + ty + 8 * j) * C + c0 + tx];
    __syncthreads();
    __half* pout = out + (size_t)e * R * C;
    #pragma unroll
    for (int j = 0; j < 4; j++) {
        size_t o = (size_t)(c0 + ty + 8 * j) * R + r0 + tx;
        pout[o] = __float2half_rn(tile[tx][ty + 8 * j]);
    }
}

// ---------------- fp16 mma.sync GEMM ----------------
// CTA tile 128 (M=tokens) x 128 (N=features), 256 threads, warp tile 64x32.
// BK=64 (128B rows), 3-stage cp.async pipeline, 2 CTAs resident per SM.
// C[t][f] = sum_k A[t][k] * B[f][k]
template <int KTOT, int F, bool GELU>
__global__ __launch_bounds__(256, 2)
void gemm_h_kernel(const __half* __restrict__ A,
                   const __half* __restrict__ B,
                   const float* __restrict__ bias,
                   float* __restrict__ outF,
                   __half* __restrict__ outH) {
    constexpr int S  = 3;
    constexpr int BK = 64;                    // 128B rows
    constexpr int NK = KTOT / BK;
    constexpr uint32_t OFF_A = 0;             // A: 128 rows x 128B = 16 KB
    constexpr uint32_t OFF_B = 16384;         // B: 128 rows x 128B = 16 KB
    constexpr uint32_t STAGE_B = 32768;       // 32 KB

    extern __shared__ char dynsmem[];
    const uint32_t sm0 = smem_u32(dynsmem);

    const int tid  = threadIdx.x;
    const int wid  = tid >> 5;
    const int lane = tid & 31;
    const int wm   = wid & 1;      // 2 warp rows  (M: 64 each)
    const int wn   = wid >> 1;     // 4 warp cols  (N: 32 each)

    const int m0 = blockIdx.y * 128;
    const int n0 = blockIdx.x * 128;
    const __half* pA = A + (size_t)blockIdx.z * NT * KTOT + (size_t)m0 * KTOT;
    const __half* pB = B + (size_t)blockIdx.z * F  * KTOT + (size_t)n0 * KTOT;

    // ---- precomputed cp.async offsets (256 threads) ----
    uint32_t dstT[4]; uint32_t srcT[4];       // byte offsets
    #pragma unroll
    for (int l = 0; l < 4; l++) {
        int idx = l * 256 + tid, row = idx >> 3, ch = idx & 7;
        dstT[l] = swz(row, ch);
        srcT[l] = (uint32_t)(row * KTOT + ch * 8) * 2u;   // bytes
    }

    auto load_chunk = [&](uint32_t sb, int k0) {
        const char* bA = reinterpret_cast<const char*>(pA + k0);
        const char* bB = reinterpret_cast<const char*>(pB + k0);
        #pragma unroll
        for (int l = 0; l < 4; l++)
            cp16(sb + OFF_A + dstT[l], bA + srcT[l]);
        #pragma unroll
        for (int l = 0; l < 4; l++)
            cp16(sb + OFF_B + dstT[l], bB + srcT[l]);
        CP_COMMIT();
    };

    // ---- precomputed ldmatrix offsets (k16 step via ^ (k16<<5)) ----
    const int lrow = lane & 15;
    const int lch  = lane >> 4;
    uint32_t offA[4], offB[2];
    #pragma unroll
    for (int mt = 0; mt < 4; mt++)
        offA[mt] = OFF_A + swz((uint32_t)(wm * 64 + mt * 16 + lrow), (uint32_t)lch);
    #pragma unroll
    for (int nb = 0; nb < 2; nb++)
        offB[nb] = OFF_B + swz((uint32_t)(wn * 32 + nb * 16 + lrow), (uint32_t)lch);

    float acc[4][4][4];
    #pragma unroll
    for (int i = 0; i < 4; i++)
        #pragma unroll
        for (int j = 0; j < 4; j++)
            #pragma unroll
            for (int c = 0; c < 4; c++) acc[i][j][c] = 0.f;

    // prefill
    load_chunk(sm0, 0);
    load_chunk(sm0 + STAGE_B, BK);

    uint32_t csb = sm0;                    // compute stage base
    uint32_t lsb = sm0 + 2 * STAGE_B;      // load stage base

    uint32_t a[2][4][4];                   // double-buffered A frags

    #pragma unroll 1
    for (int i = 0; i < NK; i++) {
        asm volatile("cp.async.wait_group %0;" :: "n"(S - 2) : "memory");
        __syncthreads();

        const int j = i + S - 1;
        if (j < NK) {
            load_chunk(lsb, j * BK);
            lsb += STAGE_B; if (lsb == sm0 + 3 * STAGE_B) lsb = sm0;
        } else {
            CP_COMMIT();
        }

        // prefetch A frags for k16 = 0
        #pragma unroll
        for (int mt = 0; mt < 4; mt++) ldsm4(a[0][mt], csb + offA[mt]);

        #pragma unroll
        for (int k16 = 0; k16 < 4; k16++) {
            const int cur = k16 & 1;
            const uint32_t kx  = (uint32_t)k16 << 5;
            const uint32_t kxn = (uint32_t)(k16 + 1) << 5;
            uint32_t u0[4], u1[4];
            ldsm4(u0, csb + (offB[0] ^ kx));    // n-tiles 0,1
            ldsm4(u1, csb + (offB[1] ^ kx));    // n-tiles 2,3
            #pragma unroll
            for (int mt = 0; mt < 4; mt++) {
                mma16816(acc[mt][0], a[cur][mt], u0[0], u0[2]);
                mma16816(acc[mt][1], a[cur][mt], u0[1], u0[3]);
                mma16816(acc[mt][2], a[cur][mt], u1[0], u1[2]);
                mma16816(acc[mt][3], a[cur][mt], u1[1], u1[3]);
                if (k16 < 3)                      // interleaved A prefetch
                    ldsm4(a[cur ^ 1][mt], csb + (offA[mt] ^ kxn));
            }
        }
        csb += STAGE_B; if (csb == sm0 + 3 * STAGE_B) csb = sm0;
    }

    // ---------------- epilogue ----------------
    const size_t eOut = (size_t)blockIdx.z * NT * F;
    #pragma unroll
    for (int mt = 0; mt < 4; mt++) {
        #pragma unroll
        for (int nt = 0; nt < 4; nt++) {
            const int n = n0 + wn * 32 + nt * 8 + (lane & 3) * 2;
            const float2 bv = *reinterpret_cast<const float2*>(&bias[n]);
            #pragma unroll
            for (int half = 0; half < 2; half++) {
                const int m = m0 + wm * 64 + mt * 16 + (lane >> 2) + half * 8;
                float v0 = acc[mt][nt][2 * half + 0] + bv.x;
                float v1 = acc[mt][nt][2 * half + 1] + bv.y;
                const size_t o = eOut + (size_t)m * F + n;
                if (GELU) {
                    v0 = 0.5f * v0 * (1.0f + erff(v0 * 0.70710678118654752f));
                    v1 = 0.5f * v1 * (1.0f + erff(v1 * 0.70710678118654752f));
                    *reinterpret_cast<ushort2*>(&outH[o]) = make_ushort2(
                        __half_as_ushort(__float2half_rn(v0)),
                        __half_as_ushort(__float2half_rn(v1)));
                } else {
                    *reinterpret_cast<float2*>(&outF[o]) = make_float2(v0, v1);
                }
            }
        }
    }
}

// ---------------- launch ----------------
extern "C" void kernel_launch(void* const* d_in, const int* in_sizes, int n_in,
                              void* d_out, int out_size) {
    const float* x  = (const float*)d_in[0];
    const float* w1 = (const float*)d_in[1];
    const float* w2 = (const float*)d_in[2];
    const float* b1 = (const float*)d_in[3];
    const float* b2 = (const float*)d_in[4];
    float* out = (float*)d_out;

    __half *xh, *w1t, *w2t, *hid;
    cudaGetSymbolAddress((void**)&xh,  g_x);
    cudaGetSymbolAddress((void**)&w1t, g_w1t);
    cudaGetSymbolAddress((void**)&w2t, g_w2t);
    cudaGetSymbolAddress((void**)&hid, g_h);

    const int SMEM_BYTES = 3 * 32768;   // 96 KB per CTA
    cudaFuncSetAttribute(gemm_h_kernel<DD, HH, true>,
                         cudaFuncAttributeMaxDynamicSharedMemorySize, SMEM_BYTES);
    cudaFuncSetAttribute(gemm_h_kernel<HH, DD, false>,
                         cudaFuncAttributeMaxDynamicSharedMemorySize, SMEM_BYTES);

    // ONE side stream + two events (host-side objects only; no device memory).
    // Minimal fork: only transpose_w2 (needed first by GEMM2) runs on the side
    // stream, overlapping everything up to and including GEMM1.
    cudaStream_t s2;
    cudaStreamCreateWithFlags(&s2, cudaStreamNonBlocking);
    cudaEvent_t eFork, eW2;
    cudaEventCreateWithFlags(&eFork, cudaEventDisableTiming);
    cudaEventCreateWithFlags(&eW2,   cudaEventDisableTiming);

    // fork from the capture (default) stream
    cudaEventRecord(eFork, 0);
    cudaStreamWaitEvent(s2, eFork, 0);

    // side stream: transpose+cast w2: [e][HH][DD] -> [e][DD][HH]
    transpose_h_kernel<<<dim3(DD / 32, HH / 32, NE), dim3(32, 8), 0, s2>>>(w2, w2t, HH, DD);
    cudaEventRecord(eW2, s2);

    // main stream: cast x, transpose w1, GEMM1
    {
        size_t n4 = (size_t)NE * NT * DD / 4;
        convert_h_kernel<<<(unsigned)((n4 + 255) / 256), 256>>>(x, xh, n4);
    }
    transpose_h_kernel<<<dim3(HH / 32, DD / 32, NE), dim3(32, 8)>>>(w1, w1t, DD, HH);

    gemm_h_kernel<DD, HH, true><<<dim3(HH / 128, NT / 128, NE), 256, SMEM_BYTES>>>(
        xh, w1t, b1, nullptr, hid);

    // join: GEMM2 needs w2t from the side stream
    cudaStreamWaitEvent(0, eW2, 0);
    gemm_h_kernel<HH, DD, false><<<dim3(DD / 128, NT / 128, NE), 256, SMEM_BYTES>>>(
        hid, w2t, b2, out, nullptr);
}

// round 16
// speedup vs baseline: 1.0093x; 1.0077x over previous
#include <cuda_runtime.h>
#include <cuda_fp16.h>
#include <math.h>
#include <stdint.h>

// ---------------- problem constants ----------------
#define NE   16      // experts
#define NT   2048    // tokens per expert
#define DD   1024    // model dim
#define HH   4096    // hidden dim

// ---------------- scratch (device globals; allocation-guard legal) ----------
__device__ __half g_x  [(size_t)NE * NT * DD];   // [e][t][d]
__device__ __half g_w1t[(size_t)NE * HH * DD];   // [e][h][d]
__device__ __half g_w2t[(size_t)NE * DD * HH];   // [e][d][h]
__device__ __half g_h  [(size_t)NE * NT * HH];   // [e][t][h]

// ---------------- helpers ----------------
__device__ __forceinline__ uint32_t smem_u32(const void* p) {
    uint32_t a;
    asm("{ .reg .u64 t; cvta.to.shared.u64 t, %1; cvt.u32.u64 %0, t; }" : "=r"(a) : "l"(p));
    return a;
}

__device__ __forceinline__ void cp16(uint32_t dst, const void* src) {
    asm volatile("cp.async.cg.shared.global [%0], [%1], 16;" :: "r"(dst), "l"(src));
}
#define CP_COMMIT() asm volatile("cp.async.commit_group;" ::: "memory")

__device__ __forceinline__ void ldsm4(uint32_t* r, uint32_t addr) {
    asm volatile("ldmatrix.sync.aligned.m8n8.x4.shared.b16 {%0,%1,%2,%3}, [%4];"
                 : "=r"(r[0]), "=r"(r[1]), "=r"(r[2]), "=r"(r[3]) : "r"(addr));
}

__device__ __forceinline__ void mma16816(float* d, const uint32_t* a,
                                         const uint32_t b0, const uint32_t b1) {
    asm volatile(
        "mma.sync.aligned.m16n8k16.row.col.f32.f16.f16.f32 "
        "{%0,%1,%2,%3}, {%4,%5,%6,%7}, {%8,%9}, {%0,%1,%2,%3};"
        : "+f"(d[0]), "+f"(d[1]), "+f"(d[2]), "+f"(d[3])
        : "r"(a[0]), "r"(a[1]), "r"(a[2]), "r"(a[3]), "r"(b0), "r"(b1));
}

// swizzle for 128B-row tiles: 16B chunk XORed with (row & 7)
__device__ __forceinline__ uint32_t swz(uint32_t row, uint32_t ch) {
    return row * 128u + ((ch ^ (row & 7u)) << 4);
}

// ---------------- conversion kernels ----------------
__global__ void convert_h_kernel(const float* __restrict__ in,
                                 __half* __restrict__ out, size_t n4) {
    size_t i = (size_t)blockIdx.x * blockDim.x + threadIdx.x;
    if (i >= n4) return;
    float4 v = reinterpret_cast<const float4*>(in)[i];
    reinterpret_cast<ushort4*>(out)[i] = make_ushort4(
        __half_as_ushort(__float2half_rn(v.x)), __half_as_ushort(__float2half_rn(v.y)),
        __half_as_ushort(__float2half_rn(v.z)), __half_as_ushort(__float2half_rn(v.w)));
}

// in: [E][R][C] fp32, out: [E][C][R] fp16  (256-thread version, pre-GEMM)
__global__ void transpose_h_kernel(const float* __restrict__ in,
                                   __half* __restrict__ out, int R, int C) {
    __shared__ float tile[32][33];
    int e = blockIdx.z;
    int c0 = blockIdx.x * 32, r0 = blockIdx.y * 32;
    int tx = threadIdx.x, ty = threadIdx.y;   // 32 x 8
    const float* pin = in + (size_t)e * R * C;
    #pragma unroll
    for (int j = 0; j < 4; j++)
        tile[ty + 8 * j][tx] = pin[(size_t)(r0 + ty + 8 * j) * C + c0 + tx];
    __syncthreads();
    __half* pout = out + (size_t)e * R * C;
    #pragma unroll
    for (int j = 0; j < 4; j++) {
        size_t o = (size_t)(c0 + ty + 8 * j) * R + r0 + tx;
        pout[o] = __float2half_rn(tile[tx][ty + 8 * j]);
    }
}

// 64-thread low-footprint variant — co-residable next to 2 GEMM CTAs
// (64 thr x ~32 regs = 2K regs, 4.2 KB smem fit in the freed headroom).
__global__ __launch_bounds__(64)
void transpose_h64_kernel(const float* __restrict__ in,
                          __half* __restrict__ out, int R, int C) {
    __shared__ float tile[32][33];
    int e = blockIdx.z;
    int c0 = blockIdx.x * 32, r0 = blockIdx.y * 32;
    int tx = threadIdx.x, ty = threadIdx.y;   // 32 x 2
    const float* pin = in + (size_t)e * R * C;
    #pragma unroll
    for (int j = 0; j < 16; j++)
        tile[ty + 2 * j][tx] = pin[(size_t)(r0 + ty + 2 * j) * C + c0 + tx];
    __syncthreads();
    __half* pout = out + (size_t)e * R * C;
    #pragma unroll
    for (int j = 0; j < 16; j++) {
        size_t o = (size_t)(c0 + ty + 2 * j) * R + r0 + tx;
        pout[o] = __float2half_rn(tile[tx][ty + 2 * j]);
    }
}

// ---------------- fp16 mma.sync GEMM ----------------
// CTA tile 128 (M=tokens) x 128 (N=features), 256 threads, warp tile 64x32.
// BK=64 (128B rows), 3-stage cp.async pipeline, 2 CTAs resident per SM.
// Single-buffered A frags (double-buffer proven neutral; saves 16 regs so
// prep CTAs can co-reside).
// C[t][f] = sum_k A[t][k] * B[f][k]
template <int KTOT, int F, bool GELU>
__global__ __launch_bounds__(256, 2)
void gemm_h_kernel(const __half* __restrict__ A,
                   const __half* __restrict__ B,
                   const float* __restrict__ bias,
                   float* __restrict__ outF,
                   __half* __restrict__ outH) {
    constexpr int S  = 3;
    constexpr int BK = 64;                    // 128B rows
    constexpr int NK = KTOT / BK;
    constexpr uint32_t OFF_A = 0;             // A: 128 rows x 128B = 16 KB
    constexpr uint32_t OFF_B = 16384;         // B: 128 rows x 128B = 16 KB
    constexpr uint32_t STAGE_B = 32768;       // 32 KB

    extern __shared__ char dynsmem[];
    const uint32_t sm0 = smem_u32(dynsmem);

    const int tid  = threadIdx.x;
    const int wid  = tid >> 5;
    const int lane = tid & 31;
    const int wm   = wid & 1;      // 2 warp rows  (M: 64 each)
    const int wn   = wid >> 1;     // 4 warp cols  (N: 32 each)

    const int m0 = blockIdx.y * 128;
    const int n0 = blockIdx.x * 128;
    const __half* pA = A + (size_t)blockIdx.z * NT * KTOT + (size_t)m0 * KTOT;
    const __half* pB = B + (size_t)blockIdx.z * F  * KTOT + (size_t)n0 * KTOT;

    // ---- precomputed cp.async offsets (256 threads) ----
    uint32_t dstT[4]; uint32_t srcT[4];       // byte offsets
    #pragma unroll
    for (int l = 0; l < 4; l++) {
        int idx = l * 256 + tid, row = idx >> 3, ch = idx & 7;
        dstT[l] = swz(row, ch);
        srcT[l] = (uint32_t)(row * KTOT + ch * 8) * 2u;   // bytes
    }

    auto load_chunk = [&](uint32_t sb, int k0) {
        const char* bA = reinterpret_cast<const char*>(pA + k0);
        const char* bB = reinterpret_cast<const char*>(pB + k0);
        #pragma unroll
        for (int l = 0; l < 4; l++)
            cp16(sb + OFF_A + dstT[l], bA + srcT[l]);
        #pragma unroll
        for (int l = 0; l < 4; l++)
            cp16(sb + OFF_B + dstT[l], bB + srcT[l]);
        CP_COMMIT();
    };

    // ---- precomputed ldmatrix offsets (k16 step via ^ (k16<<5)) ----
    const int lrow = lane & 15;
    const int lch  = lane >> 4;
    uint32_t offA[4], offB[2];
    #pragma unroll
    for (int mt = 0; mt < 4; mt++)
        offA[mt] = OFF_A + swz((uint32_t)(wm * 64 + mt * 16 + lrow), (uint32_t)lch);
    #pragma unroll
    for (int nb = 0; nb < 2; nb++)
        offB[nb] = OFF_B + swz((uint32_t)(wn * 32 + nb * 16 + lrow), (uint32_t)lch);

    float acc[4][4][4];
    #pragma unroll
    for (int i = 0; i < 4; i++)
        #pragma unroll
        for (int j = 0; j < 4; j++)
            #pragma unroll
            for (int c = 0; c < 4; c++) acc[i][j][c] = 0.f;

    // prefill
    load_chunk(sm0, 0);
    load_chunk(sm0 + STAGE_B, BK);

    uint32_t csb = sm0;                    // compute stage base
    uint32_t lsb = sm0 + 2 * STAGE_B;      // load stage base

    #pragma unroll 1
    for (int i = 0; i < NK; i++) {
        asm volatile("cp.async.wait_group %0;" :: "n"(S - 2) : "memory");
        __syncthreads();

        const int j = i + S - 1;
        if (j < NK) {
            load_chunk(lsb, j * BK);
            lsb += STAGE_B; if (lsb == sm0 + 3 * STAGE_B) lsb = sm0;
        } else {
            CP_COMMIT();
        }

        #pragma unroll
        for (int k16 = 0; k16 < 4; k16++) {
            const uint32_t kx = (uint32_t)k16 << 5;
            uint32_t a[4][4], u0[4], u1[4];
            #pragma unroll
            for (int mt = 0; mt < 4; mt++) ldsm4(a[mt], csb + (offA[mt] ^ kx));
            ldsm4(u0, csb + (offB[0] ^ kx));    // n-tiles 0,1
            ldsm4(u1, csb + (offB[1] ^ kx));    // n-tiles 2,3
            #pragma unroll
            for (int mt = 0; mt < 4; mt++) {
                mma16816(acc[mt][0], a[mt], u0[0], u0[2]);
                mma16816(acc[mt][1], a[mt], u0[1], u0[3]);
                mma16816(acc[mt][2], a[mt], u1[0], u1[2]);
                mma16816(acc[mt][3], a[mt], u1[1], u1[3]);
            }
        }
        csb += STAGE_B; if (csb == sm0 + 3 * STAGE_B) csb = sm0;
    }

    // ---------------- epilogue ----------------
    const size_t eOut = (size_t)blockIdx.z * NT * F;
    #pragma unroll
    for (int mt = 0; mt < 4; mt++) {
        #pragma unroll
        for (int nt = 0; nt < 4; nt++) {
            const int n = n0 + wn * 32 + nt * 8 + (lane & 3) * 2;
            const float2 bv = *reinterpret_cast<const float2*>(&bias[n]);
            #pragma unroll
            for (int half = 0; half < 2; half++) {
                const int m = m0 + wm * 64 + mt * 16 + (lane >> 2) + half * 8;
                float v0 = acc[mt][nt][2 * half + 0] + bv.x;
                float v1 = acc[mt][nt][2 * half + 1] + bv.y;
                const size_t o = eOut + (size_t)m * F + n;
                if (GELU) {
                    v0 = 0.5f * v0 * (1.0f + erff(v0 * 0.70710678118654752f));
                    v1 = 0.5f * v1 * (1.0f + erff(v1 * 0.70710678118654752f));
                    *reinterpret_cast<ushort2*>(&outH[o]) = make_ushort2(
                        __half_as_ushort(__float2half_rn(v0)),
                        __half_as_ushort(__float2half_rn(v1)));
                } else {
                    *reinterpret_cast<float2*>(&outF[o]) = make_float2(v0, v1);
                }
            }
        }
    }
}

// ---------------- launch ----------------
extern "C" void kernel_launch(void* const* d_in, const int* in_sizes, int n_in,
                              void* d_out, int out_size) {
    const float* x  = (const float*)d_in[0];
    const float* w1 = (const float*)d_in[1];
    const float* w2 = (const float*)d_in[2];
    const float* b1 = (const float*)d_in[3];
    const float* b2 = (const float*)d_in[4];
    float* out = (float*)d_out;

    __half *xh, *w1t, *w2t, *hid;
    cudaGetSymbolAddress((void**)&xh,  g_x);
    cudaGetSymbolAddress((void**)&w1t, g_w1t);
    cudaGetSymbolAddress((void**)&w2t, g_w2t);
    cudaGetSymbolAddress((void**)&hid, g_h);

    const int SMEM_BYTES = 3 * 32768;   // 96 KB per CTA
    cudaFuncSetAttribute(gemm_h_kernel<DD, HH, true>,
                         cudaFuncAttributeMaxDynamicSharedMemorySize, SMEM_BYTES);
    cudaFuncSetAttribute(gemm_h_kernel<HH, DD, false>,
                         cudaFuncAttributeMaxDynamicSharedMemorySize, SMEM_BYTES);

    // ONE side stream + two events (R15-validated capture pattern).
    cudaStream_t s2;
    cudaStreamCreateWithFlags(&s2, cudaStreamNonBlocking);
    cudaEvent_t eFork, eW2;
    cudaEventCreateWithFlags(&eFork, cudaEventDisableTiming);
    cudaEventCreateWithFlags(&eW2,   cudaEventDisableTiming);

    // fork from the capture (default) stream
    cudaEventRecord(eFork, 0);
    cudaStreamWaitEvent(s2, eFork, 0);

    // side stream: transpose+cast w2 with the LOW-FOOTPRINT 64-thread kernel
    // so its CTAs co-reside with GEMM1's (which now leave reg/smem headroom).
    transpose_h64_kernel<<<dim3(DD / 32, HH / 32, NE), dim3(32, 2), 0, s2>>>(w2, w2t, HH, DD);
    cudaEventRecord(eW2, s2);

    // main stream: cast x, transpose w1 (full-size kernels, chip is idle here)
    {
        size_t n4 = (size_t)NE * NT * DD / 4;
        convert_h_kernel<<<(unsigned)((n4 + 255) / 256), 256>>>(x, xh, n4);
    }
    transpose_h_kernel<<<dim3(HH / 32, DD / 32, NE), dim3(32, 8)>>>(w1, w1t, DD, HH);

    gemm_h_kernel<DD, HH, true><<<dim3(HH / 128, NT / 128, NE), 256, SMEM_BYTES>>>(
        xh, w1t, b1, nullptr, hid);

    // join: GEMM2 needs w2t from the side stream
    cudaStreamWaitEvent(0, eW2, 0);
    gemm_h_kernel<HH, DD, false><<<dim3(DD / 128, NT / 128, NE), 256, SMEM_BYTES>>>(
        hid, w2t, b2, out, nullptr);
}

// round 17
// speedup vs baseline: 1.0131x; 1.0038x over previous
#include <cuda_runtime.h>
#include <cuda_fp16.h>
#include <math.h>
#include <stdint.h>

// ---------------- problem constants ----------------
#define NE   16      // experts
#define NT   2048    // tokens per expert
#define DD   1024    // model dim
#define HH   4096    // hidden dim

// ---------------- scratch (device globals; allocation-guard legal) ----------
__device__ __half g_x  [(size_t)NE * NT * DD];   // [e][t][d]
__device__ __half g_w1t[(size_t)NE * HH * DD];   // [e][h][d]
__device__ __half g_w2t[(size_t)NE * DD * HH];   // [e][d][h]
__device__ __half g_h  [(size_t)NE * NT * HH];   // [e][t][h]

// ---------------- helpers ----------------
__device__ __forceinline__ uint32_t smem_u32(const void* p) {
    uint32_t a;
    asm("{ .reg .u64 t; cvta.to.shared.u64 t, %1; cvt.u32.u64 %0, t; }" : "=r"(a) : "l"(p));
    return a;
}

__device__ __forceinline__ void cp16(uint32_t dst, const void* src) {
    asm volatile("cp.async.cg.shared.global [%0], [%1], 16;" :: "r"(dst), "l"(src));
}
#define CP_COMMIT() asm volatile("cp.async.commit_group;" ::: "memory")

__device__ __forceinline__ void ldsm4(uint32_t* r, uint32_t addr) {
    asm volatile("ldmatrix.sync.aligned.m8n8.x4.shared.b16 {%0,%1,%2,%3}, [%4];"
                 : "=r"(r[0]), "=r"(r[1]), "=r"(r[2]), "=r"(r[3]) : "r"(addr));
}

__device__ __forceinline__ void mma16816(float* d, const uint32_t* a,
                                         const uint32_t b0, const uint32_t b1) {
    asm volatile(
        "mma.sync.aligned.m16n8k16.row.col.f32.f16.f16.f32 "
        "{%0,%1,%2,%3}, {%4,%5,%6,%7}, {%8,%9}, {%0,%1,%2,%3};"
        : "+f"(d[0]), "+f"(d[1]), "+f"(d[2]), "+f"(d[3])
        : "r"(a[0]), "r"(a[1]), "r"(a[2]), "r"(a[3]), "r"(b0), "r"(b1));
}

// swizzle for 128B-row tiles: 16B chunk XORed with (row & 7)
__device__ __forceinline__ uint32_t swz(uint32_t row, uint32_t ch) {
    return row * 128u + ((ch ^ (row & 7u)) << 4);
}

// ---------------- conversion kernels ----------------
__global__ void convert_h_kernel(const float* __restrict__ in,
                                 __half* __restrict__ out, size_t n4) {
    size_t i = (size_t)blockIdx.x * blockDim.x + threadIdx.x;
    if (i >= n4) return;
    float4 v = reinterpret_cast<const float4*>(in)[i];
    reinterpret_cast<ushort4*>(out)[i] = make_ushort4(
        __half_as_ushort(__float2half_rn(v.x)), __half_as_ushort(__float2half_rn(v.y)),
        __half_as_ushort(__float2half_rn(v.z)), __half_as_ushort(__float2half_rn(v.w)));
}

// in: [E][R][C] fp32, out: [E][C][R] fp16  (256-thread version, pre-GEMM)
__global__ void transpose_h_kernel(const float* __restrict__ in,
                                   __half* __restrict__ out, int R, int C) {
    __shared__ float tile[32][33];
    int e = blockIdx.z;
    int c0 = blockIdx.x * 32, r0 = blockIdx.y * 32;
    int tx = threadIdx.x, ty = threadIdx.y;   // 32 x 8
    const float* pin = in + (size_t)e * R * C;
    #pragma unroll
    for (int j = 0; j < 4; j++)
        tile[ty + 8 * j][tx] = pin[(size_t)(r0 + ty + 8 * j) * C + c0 + tx];
    __syncthreads();
    __half* pout = out + (size_t)e * R * C;
    #pragma unroll
    for (int j = 0; j < 4; j++) {
        size_t o = (size_t)(c0 + ty + 8 * j) * R + r0 + tx;
        pout[o] = __float2half_rn(tile[tx][ty + 8 * j]);
    }
}

// 64-thread low-footprint variant — co-residable next to GEMM CTAs.
__global__ __launch_bounds__(64)
void transpose_h64_kernel(const float* __restrict__ in,
                          __half* __restrict__ out, int R, int C) {
    __shared__ float tile[32][33];
    int e = blockIdx.z;
    int c0 = blockIdx.x * 32, r0 = blockIdx.y * 32;
    int tx = threadIdx.x, ty = threadIdx.y;   // 32 x 2
    const float* pin = in + (size_t)e * R * C;
    #pragma unroll
    for (int j = 0; j < 16; j++)
        tile[ty + 2 * j][tx] = pin[(size_t)(r0 + ty + 2 * j) * C + c0 + tx];
    __syncthreads();
    __half* pout = out + (size_t)e * R * C;
    #pragma unroll
    for (int j = 0; j < 16; j++) {
        size_t o = (size_t)(c0 + ty + 2 * j) * R + r0 + tx;
        pout[o] = __float2half_rn(tile[tx][ty + 2 * j]);
    }
}

// ---------------- fp16 mma.sync GEMM ----------------
// CTA tile 128 (M=tokens) x 128 (N=features), 256 threads, warp tile 64x32.
// BK=64 (128B rows), 3-stage cp.async pipeline, 2 CTAs resident per SM.
// C[t][f] = sum_k A[t][k] * B[f][k]
template <int KTOT, int F, bool GELU>
__global__ __launch_bounds__(256, 2)
void gemm_h_kernel(const __half* __restrict__ A,
                   const __half* __restrict__ B,
                   const float* __restrict__ bias,
                   float* __restrict__ outF,
                   __half* __restrict__ outH) {
    constexpr int S  = 3;
    constexpr int BK = 64;                    // 128B rows
    constexpr int NK = KTOT / BK;
    constexpr uint32_t OFF_A = 0;             // A: 128 rows x 128B = 16 KB
    constexpr uint32_t OFF_B = 16384;         // B: 128 rows x 128B = 16 KB
    constexpr uint32_t STAGE_B = 32768;       // 32 KB

    extern __shared__ char dynsmem[];
    const uint32_t sm0 = smem_u32(dynsmem);

    const int tid  = threadIdx.x;
    const int wid  = tid >> 5;
    const int lane = tid & 31;
    const int wm   = wid & 1;      // 2 warp rows  (M: 64 each)
    const int wn   = wid >> 1;     // 4 warp cols  (N: 32 each)

    const int m0 = blockIdx.y * 128;
    const int n0 = blockIdx.x * 128;
    const __half* pA = A + (size_t)blockIdx.z * NT * KTOT + (size_t)m0 * KTOT;
    const __half* pB = B + (size_t)blockIdx.z * F  * KTOT + (size_t)n0 * KTOT;

    // ---- precomputed cp.async offsets (256 threads) ----
    uint32_t dstT[4]; uint32_t srcT[4];       // byte offsets
    #pragma unroll
    for (int l = 0; l < 4; l++) {
        int idx = l * 256 + tid, row = idx >> 3, ch = idx & 7;
        dstT[l] = swz(row, ch);
        srcT[l] = (uint32_t)(row * KTOT + ch * 8) * 2u;   // bytes
    }

    auto load_chunk = [&](uint32_t sb, int k0) {
        const char* bA = reinterpret_cast<const char*>(pA + k0);
        const char* bB = reinterpret_cast<const char*>(pB + k0);
        #pragma unroll
        for (int l = 0; l < 4; l++)
            cp16(sb + OFF_A + dstT[l], bA + srcT[l]);
        #pragma unroll
        for (int l = 0; l < 4; l++)
            cp16(sb + OFF_B + dstT[l], bB + srcT[l]);
        CP_COMMIT();
    };

    // ---- precomputed ldmatrix offsets (k16 step via ^ (k16<<5)) ----
    const int lrow = lane & 15;
    const int lch  = lane >> 4;
    uint32_t offA[4], offB[2];
    #pragma unroll
    for (int mt = 0; mt < 4; mt++)
        offA[mt] = OFF_A + swz((uint32_t)(wm * 64 + mt * 16 + lrow), (uint32_t)lch);
    #pragma unroll
    for (int nb = 0; nb < 2; nb++)
        offB[nb] = OFF_B + swz((uint32_t)(wn * 32 + nb * 16 + lrow), (uint32_t)lch);

    float acc[4][4][4];
    #pragma unroll
    for (int i = 0; i < 4; i++)
        #pragma unroll
        for (int j = 0; j < 4; j++)
            #pragma unroll
            for (int c = 0; c < 4; c++) acc[i][j][c] = 0.f;

    // prefill
    load_chunk(sm0, 0);
    load_chunk(sm0 + STAGE_B, BK);

    uint32_t csb = sm0;                    // compute stage base
    uint32_t lsb = sm0 + 2 * STAGE_B;      // load stage base

    #pragma unroll 1
    for (int i = 0; i < NK; i++) {
        asm volatile("cp.async.wait_group %0;" :: "n"(S - 2) : "memory");
        __syncthreads();

        const int j = i + S - 1;
        if (j < NK) {
            load_chunk(lsb, j * BK);
            lsb += STAGE_B; if (lsb == sm0 + 3 * STAGE_B) lsb = sm0;
        } else {
            CP_COMMIT();
        }

        #pragma unroll
        for (int k16 = 0; k16 < 4; k16++) {
            const uint32_t kx = (uint32_t)k16 << 5;
            uint32_t a[4][4], u0[4], u1[4];
            #pragma unroll
            for (int mt = 0; mt < 4; mt++) ldsm4(a[mt], csb + (offA[mt] ^ kx));
            ldsm4(u0, csb + (offB[0] ^ kx));    // n-tiles 0,1
            ldsm4(u1, csb + (offB[1] ^ kx));    // n-tiles 2,3
            #pragma unroll
            for (int mt = 0; mt < 4; mt++) {
                mma16816(acc[mt][0], a[mt], u0[0], u0[2]);
                mma16816(acc[mt][1], a[mt], u0[1], u0[3]);
                mma16816(acc[mt][2], a[mt], u1[0], u1[2]);
                mma16816(acc[mt][3], a[mt], u1[1], u1[3]);
            }
        }
        csb += STAGE_B; if (csb == sm0 + 3 * STAGE_B) csb = sm0;
    }

    // ---------------- epilogue ----------------
    const size_t eOut = (size_t)blockIdx.z * NT * F;
    #pragma unroll
    for (int mt = 0; mt < 4; mt++) {
        #pragma unroll
        for (int nt = 0; nt < 4; nt++) {
            const int n = n0 + wn * 32 + nt * 8 + (lane & 3) * 2;
            const float2 bv = *reinterpret_cast<const float2*>(&bias[n]);
            #pragma unroll
            for (int half = 0; half < 2; half++) {
                const int m = m0 + wm * 64 + mt * 16 + (lane >> 2) + half * 8;
                float v0 = acc[mt][nt][2 * half + 0] + bv.x;
                float v1 = acc[mt][nt][2 * half + 1] + bv.y;
                const size_t o = eOut + (size_t)m * F + n;
                if (GELU) {
                    v0 = 0.5f * v0 * (1.0f + erff(v0 * 0.70710678118654752f));
                    v1 = 0.5f * v1 * (1.0f + erff(v1 * 0.70710678118654752f));
                    *reinterpret_cast<ushort2*>(&outH[o]) = make_ushort2(
                        __half_as_ushort(__float2half_rn(v0)),
                        __half_as_ushort(__float2half_rn(v1)));
                } else {
                    *reinterpret_cast<float2*>(&outF[o]) = make_float2(v0, v1);
                }
            }
        }
    }
}

// ---------------- launch ----------------
extern "C" void kernel_launch(void* const* d_in, const int* in_sizes, int n_in,
                              void* d_out, int out_size) {
    const float* x  = (const float*)d_in[0];
    const float* w1 = (const float*)d_in[1];
    const float* w2 = (const float*)d_in[2];
    const float* b1 = (const float*)d_in[3];
    const float* b2 = (const float*)d_in[4];
    float* out = (float*)d_out;

    __half *xh, *w1t, *w2t, *hid;
    cudaGetSymbolAddress((void**)&xh,  g_x);
    cudaGetSymbolAddress((void**)&w1t, g_w1t);
    cudaGetSymbolAddress((void**)&w2t, g_w2t);
    cudaGetSymbolAddress((void**)&hid, g_h);

    const int SMEM_BYTES = 3 * 32768;   // 96 KB per CTA
    cudaFuncSetAttribute(gemm_h_kernel<DD, HH, true>,
                         cudaFuncAttributeMaxDynamicSharedMemorySize, SMEM_BYTES);
    cudaFuncSetAttribute(gemm_h_kernel<HH, DD, false>,
                         cudaFuncAttributeMaxDynamicSharedMemorySize, SMEM_BYTES);

    // ONE side stream (R15/R16-validated capture pattern), three events.
    // Side stream: transpose_w1 (fast 256-thr) then transpose_w2 (64-thr,
    // co-residable under GEMM1). Main stream: convert_x concurrently.
    cudaStream_t s2;
    cudaStreamCreateWithFlags(&s2, cudaStreamNonBlocking);
    cudaEvent_t eFork, eW1, eW2;
    cudaEventCreateWithFlags(&eFork, cudaEventDisableTiming);
    cudaEventCreateWithFlags(&eW1,   cudaEventDisableTiming);
    cudaEventCreateWithFlags(&eW2,   cudaEventDisableTiming);

    // fork from the capture (default) stream
    cudaEventRecord(eFork, 0);
    cudaStreamWaitEvent(s2, eFork, 0);

    // side stream: w1 transpose (needed by GEMM1), then w2 transpose
    transpose_h_kernel<<<dim3(HH / 32, DD / 32, NE), dim3(32, 8), 0, s2>>>(w1, w1t, DD, HH);
    cudaEventRecord(eW1, s2);
    transpose_h64_kernel<<<dim3(DD / 32, HH / 32, NE), dim3(32, 2), 0, s2>>>(w2, w2t, HH, DD);
    cudaEventRecord(eW2, s2);

    // main stream: cast x -> fp16 (concurrent with w1 transpose)
    {
        size_t n4 = (size_t)NE * NT * DD / 4;
        convert_h_kernel<<<(unsigned)((n4 + 255) / 256), 256>>>(x, xh, n4);
    }

    // GEMM1 needs x + w1t
    cudaStreamWaitEvent(0, eW1, 0);
    gemm_h_kernel<DD, HH, true><<<dim3(HH / 128, NT / 128, NE), 256, SMEM_BYTES>>>(
        xh, w1t, b1, nullptr, hid);

    // GEMM2 additionally needs w2t (finished long before GEMM1 ends)
    cudaStreamWaitEvent(0, eW2, 0);
    gemm_h_kernel<HH, DD, false><<<dim3(DD / 128, NT / 128, NE), 256, SMEM_BYTES>>>(
        hid, w2t, b2, out, nullptr);
}